// round 1
// baseline (speedup 1.0000x reference)
#include <cuda_runtime.h>

// ---------------------------------------------------------------------------
// Talking-heads MHSA, B=2 P=2048 D=128 H=8 DF=32, fp32.
//   k1: QKV = x @ Wqkv^T  -> scatter to g_q (pre-scaled), g_k, g_v  [B,H,P,32]
//   k2: fused attention:  S_h = Q_h K_h^T ; T_g = sum_h Wtalk[g,h] S_h + bias_g
//       online softmax over keys ; O_g += P_g V_g   -> g_ctxt [B,P,H*32]
//   k3: out = ctxt @ Wproj^T
// ---------------------------------------------------------------------------

#define DEV_INLINE __device__ __forceinline__

struct U64F2 { union { unsigned long long u; float2 f; }; };

DEV_INLINE U64F2 f2fma(U64F2 a, U64F2 b, U64F2 c) {
    U64F2 d;
    asm("fma.rn.f32x2 %0, %1, %2, %3;" : "=l"(d.u) : "l"(a.u), "l"(b.u), "l"(c.u));
    return d;
}
DEV_INLINE U64F2 f2mul(U64F2 a, U64F2 b) {
    U64F2 d;
    asm("mul.rn.f32x2 %0, %1, %2;" : "=l"(d.u) : "l"(a.u), "l"(b.u));
    return d;
}
DEV_INLINE U64F2 pk2(float v) {
    U64F2 d;
    asm("mov.b64 %0, {%1, %1};" : "=l"(d.u) : "f"(v));
    return d;
}

constexpr int Bc = 2, Pc = 2048, Hc = 8, DFc = 32;
constexpr float QSCALE = 0.17677669529663687f;  // 1/sqrt(32)

__device__ float g_q[Bc * Hc * Pc * DFc];
__device__ float g_k[Bc * Hc * Pc * DFc];
__device__ float g_v[Bc * Hc * Pc * DFc];
__device__ float g_ctxt[Bc * Pc * Hc * DFc];

// ---------------------------------------------------------------------------
// GEMM: C[M,N] = A[M,K] @ Bw[N,K]^T   (both operands K-contiguous)
// EPI=0: plain store to C. EPI=1: scatter into g_q/g_k/g_v (QKV epilogue).
// M,N,K multiples of 64.
// ---------------------------------------------------------------------------
template <int EPI>
__global__ __launch_bounds__(256) void gemm_nt(const float* __restrict__ A,
                                               const float* __restrict__ Bw,
                                               float* __restrict__ C,
                                               int M, int N, int K) {
    __shared__ __align__(16) float As[64][68];  // [m][k] padded
    __shared__ __align__(16) float Bs[64][66];  // [k][n] padded

    const int tid = threadIdx.x;
    const int tx = tid & 15, ty = tid >> 4;
    const int m0 = blockIdx.x << 6, n0 = blockIdx.y << 6;

    U64F2 acc[4][2];
#pragma unroll
    for (int i = 0; i < 4; i++) {
        acc[i][0].f = make_float2(0.f, 0.f);
        acc[i][1].f = make_float2(0.f, 0.f);
    }

    for (int kc = 0; kc < K; kc += 64) {
#pragma unroll
        for (int i = 0; i < 4; i++) {
            int v = tid + (i << 8);       // 0..1023 float4 chunks
            int r = v >> 4, k4 = v & 15;  // row within tile, k-chunk
            *(float4*)&As[r][k4 << 2] =
                *(const float4*)&A[(size_t)(m0 + r) * K + kc + (k4 << 2)];
            float4 bv = *(const float4*)&Bw[(size_t)(n0 + r) * K + kc + (k4 << 2)];
            Bs[(k4 << 2) + 0][r] = bv.x;
            Bs[(k4 << 2) + 1][r] = bv.y;
            Bs[(k4 << 2) + 2][r] = bv.z;
            Bs[(k4 << 2) + 3][r] = bv.w;
        }
        __syncthreads();
#pragma unroll 8
        for (int kk = 0; kk < 64; kk++) {
            U64F2 b0 = *(const U64F2*)&Bs[kk][tx << 2];
            U64F2 b1 = *(const U64F2*)&Bs[kk][(tx << 2) + 2];
#pragma unroll
            for (int i = 0; i < 4; i++) {
                U64F2 a2 = pk2(As[(ty << 2) + i][kk]);
                acc[i][0] = f2fma(a2, b0, acc[i][0]);
                acc[i][1] = f2fma(a2, b1, acc[i][1]);
            }
        }
        __syncthreads();
    }

    if (EPI == 0) {
#pragma unroll
        for (int i = 0; i < 4; i++) {
            float4 vout;
            vout.x = acc[i][0].f.x; vout.y = acc[i][0].f.y;
            vout.z = acc[i][1].f.x; vout.w = acc[i][1].f.y;
            *(float4*)&C[(size_t)(m0 + (ty << 2) + i) * N + n0 + (tx << 2)] = vout;
        }
    } else {
#pragma unroll
        for (int i = 0; i < 4; i++) {
            float vals[4] = {acc[i][0].f.x, acc[i][0].f.y, acc[i][1].f.x, acc[i][1].f.y};
            int r = m0 + (ty << 2) + i;
            int bb = r >> 11, p = r & 2047;
#pragma unroll
            for (int j = 0; j < 4; j++) {
                int c = n0 + (tx << 2) + j;
                int sgrp = c >> 8;            // 0=q 1=k 2=v
                int h = (c >> 5) & 7, d = c & 31;
                int idx = ((bb * Hc + h) * Pc + p) * DFc + d;
                if (sgrp == 0)      g_q[idx] = vals[j] * QSCALE;
                else if (sgrp == 1) g_k[idx] = vals[j];
                else                g_v[idx] = vals[j];
            }
        }
    }
}

// ---------------------------------------------------------------------------
// Fused talking-heads attention.
// grid.x = (P/32)*B, blockIdx.x = ptile*2 + b  (b fastest so both batches
// stream the same bias tile concurrently -> L2 dedupe of the 536MB read).
// 256 threads; warp = head, lane = query row (phases 1/3) or key col (phase 2).
// ---------------------------------------------------------------------------
struct AttnSmem {
    float Ks[8][32][32];
    float Vs[8][32][32];
    float Bs[8][32][32];   // bias tile [g][p][kq]
    float Ss[8][32][33];   // raw scores, padded
    float Ps[8][32][33];   // exp probs, padded
    float mrow[8][32];
    float lrow[8][32];
    float srow[8][32];     // per-tile rescale factor
    float Wt[64];
};

__global__ __launch_bounds__(256, 1) void attn_fused(const float* __restrict__ bias,
                                                     const float* __restrict__ wtalk) {
    extern __shared__ char smem_raw[];
    AttnSmem& s = *reinterpret_cast<AttnSmem*>(smem_raw);

    const int b = blockIdx.x & 1;
    const int p0 = (blockIdx.x >> 1) * 32;
    const int tid = threadIdx.x;
    const int warp = tid >> 5, lane = tid & 31;

    if (tid < 64) s.Wt[tid] = wtalk[tid];
    (&s.mrow[0][0])[tid] = -1e30f;
    (&s.lrow[0][0])[tid] = 0.f;

    // Q rows for (head=warp, p=p0+lane), pre-scaled, into registers.
    U64F2 q[16];
    {
        const float4* qp =
            (const float4*)&g_q[((size_t)(b * Hc + warp) * Pc + p0 + lane) * DFc];
#pragma unroll
        for (int i = 0; i < 8; i++) {
            float4 v = qp[i];
            q[2 * i].f     = make_float2(v.x, v.y);
            q[2 * i + 1].f = make_float2(v.z, v.w);
        }
    }
    U64F2 o[16];
#pragma unroll
    for (int i = 0; i < 16; i++) o[i].f = make_float2(0.f, 0.f);

    const float4* kb4 = (const float4*)&g_k[(size_t)b * Hc * Pc * DFc];
    const float4* vb4 = (const float4*)&g_v[(size_t)b * Hc * Pc * DFc];
    const float4* bias4 = (const float4*)bias;

    float wv[8];
#pragma unroll
    for (int hh = 0; hh < 8; hh++) wv[hh] = wtalk[warp * 8 + hh];

    __syncthreads();

    for (int t = 0; t < Pc / 32; t++) {
        const int kq0 = t * 32;

        // ---- phase 0: stage K, V, bias tiles ----
#pragma unroll
        for (int i = 0; i < 8; i++) {
            int v = tid + (i << 8);       // float4 index 0..2047
            int h = v >> 8;
            int rem = v & 255;
            int row = rem >> 3;           // kq (K/V) or p (bias)
            int d4 = rem & 7;
            ((float4*)s.Ks)[v] = kb4[(size_t)(h * Pc + kq0 + row) * 8 + d4];
            ((float4*)s.Vs)[v] = vb4[(size_t)(h * Pc + kq0 + row) * 8 + d4];
            ((float4*)s.Bs)[v] =
                bias4[(size_t)(h * Pc + p0 + row) * (Pc / 4) + (kq0 >> 2) + d4];
        }
        __syncthreads();

        // ---- phase 1: S[h][p][kq] = q . k  (f32x2, dual accumulators) ----
        {
            const U64F2* kbase = (const U64F2*)&s.Ks[warp][0][0];
#pragma unroll 2
            for (int kq = 0; kq < 32; kq++) {
                const U64F2* kp = kbase + kq * 16;
                U64F2 a0, a1;
                a0.f = make_float2(0.f, 0.f);
                a1.f = make_float2(0.f, 0.f);
#pragma unroll
                for (int j = 0; j < 8; j++) {
                    a0 = f2fma(q[2 * j],     kp[2 * j],     a0);
                    a1 = f2fma(q[2 * j + 1], kp[2 * j + 1], a1);
                }
                s.Ss[warp][lane][kq] = (a0.f.x + a0.f.y) + (a1.f.x + a1.f.y);
            }
        }
        __syncthreads();

        // ---- phase 2: talking-heads mix + bias + online softmax ----
        // warp = output head g, lane = key column kq.
#pragma unroll 2
        for (int p = 0; p < 32; p++) {
            float tv = s.Bs[warp][p][lane];
#pragma unroll
            for (int hh = 0; hh < 8; hh++) tv = fmaf(wv[hh], s.Ss[hh][p][lane], tv);
            float mt = tv;
#pragma unroll
            for (int off = 16; off > 0; off >>= 1)
                mt = fmaxf(mt, __shfl_xor_sync(0xffffffffu, mt, off));
            float mprev = s.mrow[warp][p];
            float mnew = fmaxf(mprev, mt);
            float e = __expf(tv - mnew);
            s.Ps[warp][p][lane] = e;
            float su = e;
#pragma unroll
            for (int off = 16; off > 0; off >>= 1)
                su += __shfl_xor_sync(0xffffffffu, su, off);
            if (lane == 0) {
                float sc = __expf(mprev - mnew);
                s.srow[warp][p] = sc;
                s.mrow[warp][p] = mnew;
                s.lrow[warp][p] = s.lrow[warp][p] * sc + su;
            }
        }
        __syncthreads();

        // ---- phase 3: O rescale + P @ V  (f32x2) ----
        {
            float sc = s.srow[warp][lane];
            U64F2 sc2 = pk2(sc);
#pragma unroll
            for (int j = 0; j < 16; j++) o[j] = f2mul(o[j], sc2);
            const U64F2* vsb = (const U64F2*)&s.Vs[warp][0][0];
#pragma unroll 2
            for (int kq = 0; kq < 32; kq++) {
                U64F2 pr2 = pk2(s.Ps[warp][lane][kq]);
                const U64F2* vp = vsb + kq * 16;
#pragma unroll
                for (int j = 0; j < 16; j++) o[j] = f2fma(pr2, vp[j], o[j]);
            }
        }
        __syncthreads();
    }

    // ---- epilogue: normalize, write ctxt[b][p][g*32+d] ----
    {
        float linv = 1.0f / s.lrow[warp][lane];
        float* outp = &g_ctxt[((size_t)(b * Pc + p0 + lane) * (Hc * DFc)) + warp * DFc];
#pragma unroll
        for (int i = 0; i < 8; i++) {
            float4 v;
            v.x = o[2 * i].f.x * linv;
            v.y = o[2 * i].f.y * linv;
            v.z = o[2 * i + 1].f.x * linv;
            v.w = o[2 * i + 1].f.y * linv;
            ((float4*)outp)[i] = v;
        }
    }
}

// ---------------------------------------------------------------------------
extern "C" void kernel_launch(void* const* d_in, const int* in_sizes, int n_in,
                              void* d_out, int out_size) {
    (void)in_sizes; (void)n_in; (void)out_size;
    const float* x     = (const float*)d_in[0];
    const float* bias  = (const float*)d_in[1];
    const float* wqkv  = (const float*)d_in[2];
    const float* wtalk = (const float*)d_in[3];
    const float* wproj = (const float*)d_in[4];
    float* out = (float*)d_out;

    cudaFuncSetAttribute(attn_fused, cudaFuncAttributeMaxDynamicSharedMemorySize,
                         (int)sizeof(AttnSmem));

    void* ctxt_ptr = nullptr;
    cudaGetSymbolAddress(&ctxt_ptr, g_ctxt);

    // 1) QKV projection: [4096,128] @ [768,128]^T, scatter into g_q/g_k/g_v
    gemm_nt<1><<<dim3(64, 12), 256>>>(x, wqkv, nullptr, Bc * Pc, 3 * Hc * DFc, 128);

    // 2) fused talking-heads attention -> g_ctxt
    attn_fused<<<(Pc / 32) * Bc, 256, sizeof(AttnSmem)>>>(bias, wtalk);

    // 3) output projection: [4096,256] @ [128,256]^T -> out
    gemm_nt<0><<<dim3(64, 2), 256>>>((const float*)ctxt_ptr, wproj, out,
                                     Bc * Pc, 128, Hc * DFc);
}

// round 2
// speedup vs baseline: 1.7752x; 1.7752x over previous
#include <cuda_runtime.h>

// ---------------------------------------------------------------------------
// Talking-heads MHSA, B=2 P=2048 D=128 H=8 DF=32, fp32.
//   k1: QKV = x @ Wqkv^T  -> scatter to g_q (pre-scaled), g_k, g_v  [B,H,P,32]
//   k2: fused attention (shuffle-free online softmax, bias prefetch)
//   k3: out = ctxt @ Wproj^T
// ---------------------------------------------------------------------------

#define DEV_INLINE __device__ __forceinline__

struct U64F2 { union { unsigned long long u; float2 f; }; };

DEV_INLINE U64F2 f2fma(U64F2 a, U64F2 b, U64F2 c) {
    U64F2 d;
    asm("fma.rn.f32x2 %0, %1, %2, %3;" : "=l"(d.u) : "l"(a.u), "l"(b.u), "l"(c.u));
    return d;
}
DEV_INLINE U64F2 f2mul(U64F2 a, U64F2 b) {
    U64F2 d;
    asm("mul.rn.f32x2 %0, %1, %2;" : "=l"(d.u) : "l"(a.u), "l"(b.u));
    return d;
}
DEV_INLINE U64F2 pk2(float v) {
    U64F2 d;
    asm("mov.b64 %0, {%1, %1};" : "=l"(d.u) : "f"(v));
    return d;
}

constexpr int Bc = 2, Pc = 2048, Hc = 8, DFc = 32;
constexpr float QSCALE = 0.17677669529663687f;  // 1/sqrt(32)

__device__ float g_q[Bc * Hc * Pc * DFc];
__device__ float g_k[Bc * Hc * Pc * DFc];
__device__ float g_v[Bc * Hc * Pc * DFc];
__device__ float g_ctxt[Bc * Pc * Hc * DFc];

// ---------------------------------------------------------------------------
// GEMM: C[M,N] = A[M,K] @ Bw[N,K]^T. Conflict-free B transpose staging.
// EPI=0: plain store. EPI=1: QKV scatter epilogue. M,N,K multiples of 64.
// ---------------------------------------------------------------------------
template <int EPI>
__global__ __launch_bounds__(256) void gemm_nt(const float* __restrict__ A,
                                               const float* __restrict__ Bw,
                                               float* __restrict__ C,
                                               int M, int N, int K) {
    __shared__ __align__(16) float As[64][68];  // [m][k]
    __shared__ __align__(16) float Bs[64][68];  // [k][n]

    const int tid = threadIdx.x;
    const int tx = tid & 15, ty = tid >> 4;
    const int m0 = blockIdx.x << 6, n0 = blockIdx.y << 6;
    const int bn = tid & 63;          // n index for B staging
    const int bk = (tid >> 6) << 4;   // k base (0,16,32,48)

    U64F2 acc[4][2];
#pragma unroll
    for (int i = 0; i < 4; i++) {
        acc[i][0].f = make_float2(0.f, 0.f);
        acc[i][1].f = make_float2(0.f, 0.f);
    }

    for (int kc = 0; kc < K; kc += 64) {
#pragma unroll
        for (int i = 0; i < 4; i++) {
            int v = tid + (i << 8);
            int r = v >> 4, k4 = v & 15;
            *(float4*)&As[r][k4 << 2] =
                *(const float4*)&A[(size_t)(m0 + r) * K + kc + (k4 << 2)];
        }
#pragma unroll
        for (int c4 = 0; c4 < 4; c4++) {
            float4 bv =
                *(const float4*)&Bw[(size_t)(n0 + bn) * K + kc + bk + (c4 << 2)];
            Bs[bk + (c4 << 2) + 0][bn] = bv.x;   // stride-1 across lanes: no conflicts
            Bs[bk + (c4 << 2) + 1][bn] = bv.y;
            Bs[bk + (c4 << 2) + 2][bn] = bv.z;
            Bs[bk + (c4 << 2) + 3][bn] = bv.w;
        }
        __syncthreads();
#pragma unroll 8
        for (int kk = 0; kk < 64; kk++) {
            float4 b01 = *(const float4*)&Bs[kk][tx << 2];
            U64F2 b0, b1;
            b0.f = make_float2(b01.x, b01.y);
            b1.f = make_float2(b01.z, b01.w);
#pragma unroll
            for (int i = 0; i < 4; i++) {
                U64F2 a2 = pk2(As[(ty << 2) + i][kk]);
                acc[i][0] = f2fma(a2, b0, acc[i][0]);
                acc[i][1] = f2fma(a2, b1, acc[i][1]);
            }
        }
        __syncthreads();
    }

    if (EPI == 0) {
#pragma unroll
        for (int i = 0; i < 4; i++) {
            float4 vout;
            vout.x = acc[i][0].f.x; vout.y = acc[i][0].f.y;
            vout.z = acc[i][1].f.x; vout.w = acc[i][1].f.y;
            *(float4*)&C[(size_t)(m0 + (ty << 2) + i) * N + n0 + (tx << 2)] = vout;
        }
    } else {
#pragma unroll
        for (int i = 0; i < 4; i++) {
            float vals[4] = {acc[i][0].f.x, acc[i][0].f.y, acc[i][1].f.x, acc[i][1].f.y};
            int r = m0 + (ty << 2) + i;
            int bb = r >> 11, p = r & 2047;
#pragma unroll
            for (int j = 0; j < 4; j++) {
                int c = n0 + (tx << 2) + j;
                int sgrp = c >> 8;            // 0=q 1=k 2=v
                int h = (c >> 5) & 7, d = c & 31;
                int idx = ((bb * Hc + h) * Pc + p) * DFc + d;
                if (sgrp == 0)      g_q[idx] = vals[j] * QSCALE;
                else if (sgrp == 1) g_k[idx] = vals[j];
                else                g_v[idx] = vals[j];
            }
        }
    }
}

// ---------------------------------------------------------------------------
// Fused talking-heads attention, shuffle-free.
// grid.x = (P/32)*B; blockIdx.x = ptile*2 + b (batches adjacent -> bias L2 dedupe)
// 256 threads; warp = head.
// ---------------------------------------------------------------------------
struct AttnSmem {
    float Ks[8][32][32];   // [h][kq][d]
    float Vs[8][32][32];   // [h][kq][d]
    float Bs[8][32][36];   // [g][p][kq] bias tile, then mixed scores T (in place)
    float SP[8][32][33];   // [h][p][kq] raw scores S, then probs P (after barrier)
};

__global__ __launch_bounds__(256, 1) void attn_fused(const float* __restrict__ bias,
                                                     const float* __restrict__ wtalk) {
    extern __shared__ char smem_raw[];
    AttnSmem& s = *reinterpret_cast<AttnSmem*>(smem_raw);

    const int b = blockIdx.x & 1;
    const int p0 = (blockIdx.x >> 1) * 32;
    const int tid = threadIdx.x;
    const int warp = tid >> 5, lane = tid & 31;

    float wv[8];
#pragma unroll
    for (int hh = 0; hh < 8; hh++) wv[hh] = wtalk[warp * 8 + hh];

    // Q rows (head=warp, p=p0+lane), pre-scaled, into registers.
    U64F2 q[16];
    {
        const float4* qp =
            (const float4*)&g_q[((size_t)(b * Hc + warp) * Pc + p0 + lane) * DFc];
#pragma unroll
        for (int i = 0; i < 8; i++) {
            float4 v = qp[i];
            q[2 * i].f     = make_float2(v.x, v.y);
            q[2 * i + 1].f = make_float2(v.z, v.w);
        }
    }
    U64F2 o[16];
#pragma unroll
    for (int i = 0; i < 16; i++) o[i].f = make_float2(0.f, 0.f);
    float m_run = -1e30f, l_run = 0.f;   // per-lane (lane = query row)

    const float4* kb4 = (const float4*)&g_k[(size_t)b * Hc * Pc * DFc];
    const float4* vb4 = (const float4*)&g_v[(size_t)b * Hc * Pc * DFc];
    const float4* bias4 = (const float4*)bias;

    // staging decomposition of tid: 8 float4 chunks per thread
    // v = tid + i*256 : h = v>>8, row = (v&255)>>3, d4 = v&7
    float4 breg[8];
#pragma unroll
    for (int i = 0; i < 8; i++) {
        int v = tid + (i << 8);
        int h = v >> 8, row = (v & 255) >> 3, d4 = v & 7;
        breg[i] = bias4[(size_t)(h * Pc + p0 + row) * (Pc / 4) + d4];
    }

    for (int t = 0; t < Pc / 32; t++) {
        const int kq0 = t * 32;

        // ---- phase 0: stage K, V (L2), bias (from prefetch regs) ----
#pragma unroll
        for (int i = 0; i < 8; i++) {
            int v = tid + (i << 8);
            int h = v >> 8, row = (v & 255) >> 3, d4 = v & 7;
            ((float4*)s.Ks)[v] = kb4[(size_t)(h * Pc + kq0 + row) * 8 + d4];
            ((float4*)s.Vs)[v] = vb4[(size_t)(h * Pc + kq0 + row) * 8 + d4];
            *(float4*)&s.Bs[h][row][d4 << 2] = breg[i];
        }
        __syncthreads();

        // prefetch next tile's bias (hidden behind phases 1-3)
        if (t != Pc / 32 - 1) {
#pragma unroll
            for (int i = 0; i < 8; i++) {
                int v = tid + (i << 8);
                int h = v >> 8, row = (v & 255) >> 3, d4 = v & 7;
                breg[i] = bias4[(size_t)(h * Pc + p0 + row) * (Pc / 4) +
                                ((kq0 + 32) >> 2) + d4];
            }
        }

        // ---- phase 1: S[h][p(lane)][kq] = q . k ----
        {
            const float4* kbase = (const float4*)&s.Ks[warp][0][0];
#pragma unroll 4
            for (int kq = 0; kq < 32; kq++) {
                const float4* kp = kbase + (kq << 3);
                U64F2 a0, a1, a2, a3;
                a0.f = make_float2(0.f, 0.f); a1.f = a0.f; a2.f = a0.f; a3.f = a0.f;
#pragma unroll
                for (int j = 0; j < 8; j += 2) {
                    float4 k0 = kp[j], k1 = kp[j + 1];
                    U64F2 t0, t1, t2, t3;
                    t0.f = make_float2(k0.x, k0.y);
                    t1.f = make_float2(k0.z, k0.w);
                    t2.f = make_float2(k1.x, k1.y);
                    t3.f = make_float2(k1.z, k1.w);
                    a0 = f2fma(q[2 * j],     t0, a0);
                    a1 = f2fma(q[2 * j + 1], t1, a1);
                    a2 = f2fma(q[2 * j + 2], t2, a2);
                    a3 = f2fma(q[2 * j + 3], t3, a3);
                }
                s.SP[warp][lane][kq] =
                    (a0.f.x + a0.f.y) + (a1.f.x + a1.f.y) +
                    ((a2.f.x + a2.f.y) + (a3.f.x + a3.f.y));
            }
        }
        __syncthreads();

        // ---- phase 2 passA: talking-heads mix + bias, in place (warp=g, lane=kq)
#pragma unroll 4
        for (int p = 0; p < 32; p++) {
            float tv = s.Bs[warp][p][lane];
#pragma unroll
            for (int hh = 0; hh < 8; hh++) tv = fmaf(wv[hh], s.SP[hh][p][lane], tv);
            s.Bs[warp][p][lane] = tv;
        }
        __syncthreads();

        // ---- phase 2 passB: row-serial softmax, no shuffles (warp=g, lane=p)
        float sc;
        {
            float tvv[32];
            float mt = m_run;
            const float4* brow = (const float4*)&s.Bs[warp][lane][0];
#pragma unroll
            for (int kq4 = 0; kq4 < 8; kq4++) {
                float4 tq = brow[kq4];
                tvv[4 * kq4 + 0] = tq.x; tvv[4 * kq4 + 1] = tq.y;
                tvv[4 * kq4 + 2] = tq.z; tvv[4 * kq4 + 3] = tq.w;
                mt = fmaxf(mt, fmaxf(fmaxf(tq.x, tq.y), fmaxf(tq.z, tq.w)));
            }
            sc = __expf(m_run - mt);
            float su = 0.f;
#pragma unroll
            for (int kq = 0; kq < 32; kq++) {
                float e = __expf(tvv[kq] - mt);
                s.SP[warp][lane][kq] = e;   // P overwrites S (safe: barrier above)
                su += e;
            }
            m_run = mt;
            l_run = l_run * sc + su;
        }

        // ---- phase 3: O = O*sc + P @ V (warp=g, lane=p) ----
        {
            U64F2 sc2 = pk2(sc);
#pragma unroll
            for (int j = 0; j < 16; j++) o[j] = f2mul(o[j], sc2);
            const float4* vb = (const float4*)&s.Vs[warp][0][0];
#pragma unroll 2
            for (int kq = 0; kq < 32; kq++) {
                U64F2 pr2 = pk2(s.SP[warp][lane][kq]);  // own lane's writes
                const float4* vp = vb + (kq << 3);
#pragma unroll
                for (int j = 0; j < 8; j++) {
                    float4 vv = vp[j];
                    U64F2 vlo, vhi;
                    vlo.f = make_float2(vv.x, vv.y);
                    vhi.f = make_float2(vv.z, vv.w);
                    o[2 * j]     = f2fma(pr2, vlo, o[2 * j]);
                    o[2 * j + 1] = f2fma(pr2, vhi, o[2 * j + 1]);
                }
            }
        }
        __syncthreads();   // protect Ks/Vs/Bs/SP before next tile's writes
    }

    // ---- epilogue: normalize, write ctxt[b][p][g*32+d] ----
    {
        float linv = 1.0f / l_run;
        U64F2 li2 = pk2(linv);
        float* outp = &g_ctxt[((size_t)(b * Pc + p0 + lane) * (Hc * DFc)) + warp * DFc];
#pragma unroll
        for (int i = 0; i < 8; i++) {
            U64F2 lo = f2mul(o[2 * i], li2), hi = f2mul(o[2 * i + 1], li2);
            float4 v;
            v.x = lo.f.x; v.y = lo.f.y; v.z = hi.f.x; v.w = hi.f.y;
            ((float4*)outp)[i] = v;
        }
    }
}

// ---------------------------------------------------------------------------
extern "C" void kernel_launch(void* const* d_in, const int* in_sizes, int n_in,
                              void* d_out, int out_size) {
    (void)in_sizes; (void)n_in; (void)out_size;
    const float* x     = (const float*)d_in[0];
    const float* bias  = (const float*)d_in[1];
    const float* wqkv  = (const float*)d_in[2];
    const float* wtalk = (const float*)d_in[3];
    const float* wproj = (const float*)d_in[4];
    float* out = (float*)d_out;

    cudaFuncSetAttribute(attn_fused, cudaFuncAttributeMaxDynamicSharedMemorySize,
                         (int)sizeof(AttnSmem));

    void* ctxt_ptr = nullptr;
    cudaGetSymbolAddress(&ctxt_ptr, g_ctxt);

    // 1) QKV projection: [4096,128] @ [768,128]^T -> g_q/g_k/g_v
    gemm_nt<1><<<dim3(64, 12), 256>>>(x, wqkv, nullptr, Bc * Pc, 3 * Hc * DFc, 128);

    // 2) fused talking-heads attention -> g_ctxt
    attn_fused<<<(Pc / 32) * Bc, 256, sizeof(AttnSmem)>>>(bias, wtalk);

    // 3) output projection: [4096,256] @ [128,256]^T -> out
    gemm_nt<0><<<dim3(64, 2), 256>>>((const float*)ctxt_ptr, wproj, out,
                                     Bc * Pc, 128, Hc * DFc);
}